// round 15
// baseline (speedup 1.0000x reference)
#include <cuda_runtime.h>
#include <cuda_fp16.h>
#include <cstdint>

#define MM 16
#define KK 8192
#define NN 8192
#define KCH 8             // split-K chunks
#define KC 1024           // k per chunk (8 groups of 128)
#define RWW 528           // smem row stride in WORDS (32 super-steps * 16 + 16 pad; ==16 mod 32)

// fp32 partials: [KCH][M][N]
__device__ float g_partial[KCH * MM * NN];

__device__ __forceinline__ void mma16816(float c[4],
                                         unsigned a0, unsigned a1, unsigned a2, unsigned a3,
                                         unsigned b0, unsigned b1) {
    asm volatile(
        "mma.sync.aligned.m16n8k16.row.col.f32.f16.f16.f32 "
        "{%0,%1,%2,%3}, {%4,%5,%6,%7}, {%8,%9}, {%0,%1,%2,%3};\n"
        : "+f"(c[0]), "+f"(c[1]), "+f"(c[2]), "+f"(c[3])
        : "r"(a0), "r"(a1), "r"(a2), "r"(a3), "r"(b0), "r"(b1));
}

// Nibbles t,t+4 of w -> exact fp16x2 (q-8, q'-8). 3 ops: SHF+LOP3+HSUB2.
__device__ __forceinline__ unsigned dqx(unsigned w, unsigned sh4) {
    unsigned v = ((w >> sh4) & 0x000F000Fu) | 0x64006400u;   // (1024+q, 1024+q')
    __half2 hv = *reinterpret_cast<__half2*>(&v);
    __half2 r = __hsub2(hv, __float2half2_rn(1032.0f));      // exact
    return *reinterpret_cast<unsigned*>(&r);
}

// chunk-position swizzle: conflict-free for staging STS.128 and consumption LDS.128
__device__ __forceinline__ int posf(int m, int S, int t) {
    return (t + m + (m >> 2) + S + (S >> 2)) & 3;
}

__global__ __launch_bounds__(128, 4)
void q4_gemm_mma(const float* __restrict__ x,
                 const int* __restrict__ qw,
                 const float* __restrict__ scales) {
    __shared__ __align__(16) unsigned xs[MM * RWW];   // 16 rows * 528 words * 4B = 33792 B

    const int tid = threadIdx.x;
    const int kc = blockIdx.y;
    const int warp = tid >> 5;
    const int lane = tid & 31;
    const int g = lane >> 2;        // 0..7
    const int t = lane & 3;         // 0..3
    const unsigned sh4 = 4u * t;
    const int nbase = blockIdx.x * 128 + warp * 32;    // warp owns n32 (4 tiles)

    // ---- Stage x chunk [16][1024] into paired-step layout ----
    // Super-step S covers k = 32S..32S+31 (2 mma k16-steps). Per (row m, S): 4 chunks
    // of 4 words; chunk for lane-t at position posf(m,S,t):
    //   w0=(k32S+t,   k32S+4+t)  step0-b0 | w1=(k32S+8+t,  k32S+12+t) step0-b1
    //   w2=(k32S+16+t,k32S+20+t) step1-b0 | w3=(k32S+24+t, k32S+28+t) step1-b1
    for (int it = 0; it < 4; ++it) {
        int idx = it * 128 + tid;          // 512 tasks: (m, S)
        int m = idx >> 5;
        int S = idx & 31;
        const float* xp = x + (size_t)m * KK + kc * KC + S * 32;
        float f[32];
#pragma unroll
        for (int a = 0; a < 8; ++a) {
            float4 v = *reinterpret_cast<const float4*>(xp + a * 4);
            f[a * 4 + 0] = v.x; f[a * 4 + 1] = v.y;
            f[a * 4 + 2] = v.z; f[a * 4 + 3] = v.w;
        }
        const int base = m * RWW + S * 16;
#pragma unroll
        for (int tc = 0; tc < 4; ++tc) {
            __half2 h0 = __floats2half2_rn(f[tc],      f[tc + 4]);
            __half2 h1 = __floats2half2_rn(f[tc + 8],  f[tc + 12]);
            __half2 h2 = __floats2half2_rn(f[tc + 16], f[tc + 20]);
            __half2 h3 = __floats2half2_rn(f[tc + 24], f[tc + 28]);
            uint4 pk;
            pk.x = *reinterpret_cast<unsigned*>(&h0);
            pk.y = *reinterpret_cast<unsigned*>(&h1);
            pk.z = *reinterpret_cast<unsigned*>(&h2);
            pk.w = *reinterpret_cast<unsigned*>(&h3);
            *reinterpret_cast<uint4*>(&xs[base + 4 * posf(m, S, tc)]) = pk;
        }
    }
    __syncthreads();

    // ---- Main loop: 4 interleaved n8-tiles (tile j col c -> n = nbase+4c+j) ----
    float cm[4][4];
#pragma unroll
    for (int j = 0; j < 4; ++j)
#pragma unroll
        for (int r = 0; r < 4; ++r) cm[j][r] = 0.f;

    for (int grp = 0; grp < 8; ++grp) {
        const int gidx = kc * 8 + grp;
        const float4 sv0 = __ldg(reinterpret_cast<const float4*>(
            scales + (size_t)gidx * NN + nbase + 8 * t));
        const float4 sv1 = __ldg(reinterpret_cast<const float4*>(
            scales + (size_t)gidx * NN + nbase + 8 * t + 4));

        float ct[4][4];
#pragma unroll
        for (int j = 0; j < 4; ++j)
#pragma unroll
            for (int r = 0; r < 4; ++r) ct[j][r] = 0.f;

#pragma unroll
        for (int s4 = 0; s4 < 4; ++s4) {
            const int S = grp * 4 + s4;
            // A fragments for BOTH steps of this super-step: one LDS.128 per row.
            uint4 A1 = *reinterpret_cast<const uint4*>(
                &xs[g * RWW + S * 16 + 4 * posf(g, S, t)]);
            uint4 A2 = *reinterpret_cast<const uint4*>(
                &xs[(g + 8) * RWW + S * 16 + 4 * posf(g + 8, S, t)]);
            // A1 = (a0_s0, a2_s0, a0_s1, a2_s1) row g; A2 same for row g+8.

#pragma unroll
            for (int st = 0; st < 2; ++st) {
                const int row = kc * 128 + 4 * S + 2 * st;   // packed rows 2kt, 2kt+1
                const int* rp = qw + (size_t)row * NN + nbase + 4 * g;
                uint4 q0 = __ldg(reinterpret_cast<const uint4*>(rp));
                uint4 q1 = __ldg(reinterpret_cast<const uint4*>(rp + NN));

                unsigned a0 = st ? A1.z : A1.x;
                unsigned a2 = st ? A1.w : A1.y;
                unsigned a1 = st ? A2.z : A2.x;
                unsigned a3 = st ? A2.w : A2.y;

                mma16816(ct[0], a0, a1, a2, a3, dqx(q0.x, sh4), dqx(q1.x, sh4));
                mma16816(ct[1], a0, a1, a2, a3, dqx(q0.y, sh4), dqx(q1.y, sh4));
                mma16816(ct[2], a0, a1, a2, a3, dqx(q0.z, sh4), dqx(q1.z, sh4));
                mma16816(ct[3], a0, a1, a2, a3, dqx(q0.w, sh4), dqx(q1.w, sh4));
            }
        }

        // Apply group scale (R7 verbatim): col 2t -> slo[j], col 2t+1 -> shi[j]
        const float slo[4] = {sv0.x, sv0.y, sv0.z, sv0.w};
        const float shi[4] = {sv1.x, sv1.y, sv1.z, sv1.w};
#pragma unroll
        for (int j = 0; j < 4; ++j) {
            cm[j][0] += ct[j][0] * slo[j];
            cm[j][1] += ct[j][1] * shi[j];
            cm[j][2] += ct[j][2] * slo[j];
            cm[j][3] += ct[j][3] * shi[j];
        }
    }

    // ---- Store fp32 partials (tile j col c -> global col nbase+4c+j) ----
    {
        float* p = g_partial + (size_t)kc * MM * NN;
        const int col = nbase + 8 * t;
        float4 v00 = make_float4(cm[0][0], cm[1][0], cm[2][0], cm[3][0]);
        float4 v01 = make_float4(cm[0][1], cm[1][1], cm[2][1], cm[3][1]);
        float4 v10 = make_float4(cm[0][2], cm[1][2], cm[2][2], cm[3][2]);
        float4 v11 = make_float4(cm[0][3], cm[1][3], cm[2][3], cm[3][3]);
        *reinterpret_cast<float4*>(p + (size_t)g * NN + col)           = v00;
        *reinterpret_cast<float4*>(p + (size_t)g * NN + col + 4)       = v01;
        *reinterpret_cast<float4*>(p + (size_t)(g + 8) * NN + col)     = v10;
        *reinterpret_cast<float4*>(p + (size_t)(g + 8) * NN + col + 4) = v11;
    }
}

// Reduce strip: 1/4 of the output per launch (4 launches -> 5 launches/call total,
// so ncu -s 5 -c 1 lands on the GEMM kernel).
__global__ __launch_bounds__(128)
void reduce_bias_strip(const float* __restrict__ bias, float* __restrict__ out,
                       int i2_base) {
    const int i2 = i2_base + blockIdx.x * 128 + threadIdx.x;
    const float2* pp = reinterpret_cast<const float2*>(g_partial);

    float2 s = pp[i2];
#pragma unroll
    for (int c = 1; c < KCH; ++c) {
        float2 b = pp[(size_t)c * (MM * NN / 2) + i2];
        s.x += b.x; s.y += b.y;
    }

    const int idx = i2 * 2;
    const int n = idx & (NN - 1);
    float2 bv = *reinterpret_cast<const float2*>(bias + n);
    __half h0 = __hadd(__float2half_rn(s.x), __float2half_rn(bv.x));
    __half h1 = __hadd(__float2half_rn(s.y), __float2half_rn(bv.y));
    float2 o;
    o.x = __half2float(h0);
    o.y = __half2float(h1);
    *reinterpret_cast<float2*>(out + idx) = o;
}

extern "C" void kernel_launch(void* const* d_in, const int* in_sizes, int n_in,
                              void* d_out, int out_size) {
    const float* x    = nullptr;   // 131072
    const int*   qw   = nullptr;   // 8388608
    const float* sc   = nullptr;   // 524288
    const float* bias = nullptr;   // 8192
    for (int i = 0; i < n_in; ++i) {
        switch (in_sizes[i]) {
            case 131072:  x    = (const float*)d_in[i]; break;
            case 8388608: qw   = (const int*)d_in[i];   break;
            case 524288:  sc   = (const float*)d_in[i]; break;
            case 8192:    bias = (const float*)d_in[i]; break;
            default: break;
        }
    }
    float* out = (float*)d_out;

    dim3 grid(NN / 128, KCH);          // (64, 8), 128 threads (4 warps, n32 each)
    q4_gemm_mma<<<grid, 128>>>(x, qw, sc);

    const int total_i2 = MM * NN / 2;          // 65536
    const int strip = total_i2 / 4;            // 16384 -> 128 blocks each
    for (int sidx = 0; sidx < 4; ++sidx)
        reduce_bias_strip<<<strip / 128, 128>>>(bias, out, sidx * strip);
}

// round 16
// speedup vs baseline: 1.2373x; 1.2373x over previous
#include <cuda_runtime.h>
#include <cuda_fp16.h>
#include <cstdint>

#define MM 16
#define KK 8192
#define NN 8192
#define KCH 8             // split-K chunks
#define KC 1024           // k per chunk (8 groups of 128)
#define RWW 528           // smem row stride in WORDS (32 super-steps * 16 + 16 pad)

// fp32 partials: [KCH][M][N]
__device__ float g_partial[KCH * MM * NN];

__device__ __forceinline__ void mma16816(float c[4],
                                         unsigned a0, unsigned a1, unsigned a2, unsigned a3,
                                         unsigned b0, unsigned b1) {
    asm volatile(
        "mma.sync.aligned.m16n8k16.row.col.f32.f16.f16.f32 "
        "{%0,%1,%2,%3}, {%4,%5,%6,%7}, {%8,%9}, {%0,%1,%2,%3};\n"
        : "+f"(c[0]), "+f"(c[1]), "+f"(c[2]), "+f"(c[3])
        : "r"(a0), "r"(a1), "r"(a2), "r"(a3), "r"(b0), "r"(b1));
}

// Nibbles t,t+4 of w -> exact fp16x2 (q-8, q'-8). 3 ops: SHF+LOP3+HSUB2.
__device__ __forceinline__ unsigned dqx(unsigned w, unsigned sh4) {
    unsigned v = ((w >> sh4) & 0x000F000Fu) | 0x64006400u;   // (1024+q, 1024+q')
    __half2 hv = *reinterpret_cast<__half2*>(&v);
    __half2 r = __hsub2(hv, __float2half2_rn(1032.0f));      // exact
    return *reinterpret_cast<unsigned*>(&r);
}

// chunk-position swizzle: conflict-free for staging STS.128 and consumption LDS.128
__device__ __forceinline__ int posf(int m, int S, int t) {
    return (t + m + (m >> 2) + S + (S >> 2)) & 3;
}

__global__ __launch_bounds__(128, 4)
void q4_gemm_mma(const float* __restrict__ x,
                 const int* __restrict__ qw,
                 const float* __restrict__ scales) {
    __shared__ __align__(16) unsigned xs[MM * RWW];   // 33792 B

    const int tid = threadIdx.x;
    const int kc = blockIdx.y;
    const int warp = tid >> 5;
    const int lane = tid & 31;
    const int g = lane >> 2;        // 0..7
    const int t = lane & 3;         // 0..3
    const unsigned sh4 = 4u * t;
    const int nbase = blockIdx.x * 128 + warp * 32;    // warp owns n32 (4 tiles)

    // ---- Stage x chunk [16][1024] into paired-step layout ----
    // Super-step S covers k = 32S..32S+31 (2 mma k16-steps). Per (row m, S): 4 chunks
    // of 4 words; chunk for lane-t at position posf(m,S,t):
    //   w0=(k+t, k+4+t) s0-b0 | w1=(k+8+t, k+12+t) s0-b1 | w2,w3 same for step1 (+16)
    for (int it = 0; it < 4; ++it) {
        int idx = it * 128 + tid;          // 512 tasks: (m, S)
        int m = idx >> 5;
        int S = idx & 31;
        const float* xp = x + (size_t)m * KK + kc * KC + S * 32;
        float f[32];
#pragma unroll
        for (int a = 0; a < 8; ++a) {
            float4 v = *reinterpret_cast<const float4*>(xp + a * 4);
            f[a * 4 + 0] = v.x; f[a * 4 + 1] = v.y;
            f[a * 4 + 2] = v.z; f[a * 4 + 3] = v.w;
        }
        const int base = m * RWW + S * 16;
#pragma unroll
        for (int tc = 0; tc < 4; ++tc) {
            __half2 h0 = __floats2half2_rn(f[tc],      f[tc + 4]);
            __half2 h1 = __floats2half2_rn(f[tc + 8],  f[tc + 12]);
            __half2 h2 = __floats2half2_rn(f[tc + 16], f[tc + 20]);
            __half2 h3 = __floats2half2_rn(f[tc + 24], f[tc + 28]);
            uint4 pk;
            pk.x = *reinterpret_cast<unsigned*>(&h0);
            pk.y = *reinterpret_cast<unsigned*>(&h1);
            pk.z = *reinterpret_cast<unsigned*>(&h2);
            pk.w = *reinterpret_cast<unsigned*>(&h3);
            *reinterpret_cast<uint4*>(&xs[base + 4 * posf(m, S, tc)]) = pk;
        }
    }
    __syncthreads();

    // ---- Main loop: 4 interleaved n8-tiles (tile j col c -> n = nbase+4c+j) ----
    float cm[4][4];
#pragma unroll
    for (int j = 0; j < 4; ++j)
#pragma unroll
        for (int r = 0; r < 4; ++r) cm[j][r] = 0.f;

    for (int grp = 0; grp < 8; ++grp) {
        const int gidx = kc * 8 + grp;
        const float4 sv0 = __ldg(reinterpret_cast<const float4*>(
            scales + (size_t)gidx * NN + nbase + 8 * t));
        const float4 sv1 = __ldg(reinterpret_cast<const float4*>(
            scales + (size_t)gidx * NN + nbase + 8 * t + 4));

        float ct[4][4];
#pragma unroll
        for (int j = 0; j < 4; ++j)
#pragma unroll
            for (int r = 0; r < 4; ++r) ct[j][r] = 0.f;

#pragma unroll
        for (int s4 = 0; s4 < 4; ++s4) {
            const int S = grp * 4 + s4;
            // A fragments for BOTH steps of this super-step: one LDS.128 per row.
            uint4 A1 = *reinterpret_cast<const uint4*>(
                &xs[g * RWW + S * 16 + 4 * posf(g, S, t)]);
            uint4 A2 = *reinterpret_cast<const uint4*>(
                &xs[(g + 8) * RWW + S * 16 + 4 * posf(g + 8, S, t)]);
            // A1 = (a0_s0, a2_s0, a0_s1, a2_s1) row g; A2 same for row g+8.

#pragma unroll
            for (int st = 0; st < 2; ++st) {
                const int row = kc * 128 + 4 * S + 2 * st;   // packed rows 2kt, 2kt+1
                const int* rp = qw + (size_t)row * NN + nbase + 4 * g;
                uint4 q0 = __ldg(reinterpret_cast<const uint4*>(rp));
                uint4 q1 = __ldg(reinterpret_cast<const uint4*>(rp + NN));

                unsigned a0 = st ? A1.z : A1.x;
                unsigned a2 = st ? A1.w : A1.y;
                unsigned a1 = st ? A2.z : A2.x;
                unsigned a3 = st ? A2.w : A2.y;

                mma16816(ct[0], a0, a1, a2, a3, dqx(q0.x, sh4), dqx(q1.x, sh4));
                mma16816(ct[1], a0, a1, a2, a3, dqx(q0.y, sh4), dqx(q1.y, sh4));
                mma16816(ct[2], a0, a1, a2, a3, dqx(q0.z, sh4), dqx(q1.z, sh4));
                mma16816(ct[3], a0, a1, a2, a3, dqx(q0.w, sh4), dqx(q1.w, sh4));
            }
        }

        // Apply group scale: col 2t -> slo[j], col 2t+1 -> shi[j]
        const float slo[4] = {sv0.x, sv0.y, sv0.z, sv0.w};
        const float shi[4] = {sv1.x, sv1.y, sv1.z, sv1.w};
#pragma unroll
        for (int j = 0; j < 4; ++j) {
            cm[j][0] += ct[j][0] * slo[j];
            cm[j][1] += ct[j][1] * shi[j];
            cm[j][2] += ct[j][2] * slo[j];
            cm[j][3] += ct[j][3] * shi[j];
        }
    }

    // ---- Store fp32 partials (tile j col c -> global col nbase+4c+j) ----
    {
        float* p = g_partial + (size_t)kc * MM * NN;
        const int col = nbase + 8 * t;
        float4 v00 = make_float4(cm[0][0], cm[1][0], cm[2][0], cm[3][0]);
        float4 v01 = make_float4(cm[0][1], cm[1][1], cm[2][1], cm[3][1]);
        float4 v10 = make_float4(cm[0][2], cm[1][2], cm[2][2], cm[3][2]);
        float4 v11 = make_float4(cm[0][3], cm[1][3], cm[2][3], cm[3][3]);
        *reinterpret_cast<float4*>(p + (size_t)g * NN + col)           = v00;
        *reinterpret_cast<float4*>(p + (size_t)g * NN + col + 4)       = v01;
        *reinterpret_cast<float4*>(p + (size_t)(g + 8) * NN + col)     = v10;
        *reinterpret_cast<float4*>(p + (size_t)(g + 8) * NN + col + 4) = v11;
    }
}

// Single full-size reduce (R7 config, measured 4.86us).
__global__ __launch_bounds__(128)
void reduce_bias_kernel(const float* __restrict__ bias, float* __restrict__ out) {
    const int i2 = blockIdx.x * 128 + threadIdx.x;
    const float2* pp = reinterpret_cast<const float2*>(g_partial);

    float2 s = pp[i2];
#pragma unroll
    for (int c = 1; c < KCH; ++c) {
        float2 b = pp[(size_t)c * (MM * NN / 2) + i2];
        s.x += b.x; s.y += b.y;
    }

    const int idx = i2 * 2;
    const int n = idx & (NN - 1);
    float2 bv = *reinterpret_cast<const float2*>(bias + n);
    // Reference fp16 epilogue: fp16(dot) + fp16(bias) in fp16.
    __half h0 = __hadd(__float2half_rn(s.x), __float2half_rn(bv.x));
    __half h1 = __hadd(__float2half_rn(s.y), __float2half_rn(bv.y));
    float2 o;
    o.x = __half2float(h0);
    o.y = __half2float(h1);
    *reinterpret_cast<float2*>(out + idx) = o;
}

extern "C" void kernel_launch(void* const* d_in, const int* in_sizes, int n_in,
                              void* d_out, int out_size) {
    const float* x    = nullptr;   // 131072
    const int*   qw   = nullptr;   // 8388608
    const float* sc   = nullptr;   // 524288
    const float* bias = nullptr;   // 8192
    for (int i = 0; i < n_in; ++i) {
        switch (in_sizes[i]) {
            case 131072:  x    = (const float*)d_in[i]; break;
            case 8388608: qw   = (const int*)d_in[i];   break;
            case 524288:  sc   = (const float*)d_in[i]; break;
            case 8192:    bias = (const float*)d_in[i]; break;
            default: break;
        }
    }
    float* out = (float*)d_out;

    dim3 grid(NN / 128, KCH);          // (64, 8), 128 threads (4 warps, n32 each)
    q4_gemm_mma<<<grid, 128>>>(x, qw, sc);

    reduce_bias_kernel<<<(MM * NN / 2) / 128, 128>>>(bias, out);
}